// round 16
// baseline (speedup 1.0000x reference)
#include <cuda_runtime.h>
#include <cuda_bf16.h>

#define B_ 8
#define C_ 512
#define HW 1024
#define NH 8
#define DH 64
#define OC_QKV 1536

typedef __nv_bfloat16 bf16;

// -------- scratch (static device globals; no allocation) --------
__device__ bf16 g_h[B_ * C_ * HW];
__device__ bf16 g_qkv[B_ * OC_QKV * HW];
__device__ bf16 g_att[B_ * C_ * HW];
__device__ bf16 g_wq[OC_QKV * C_];
__device__ bf16 g_wp[C_ * C_];

// -------- helpers --------
__device__ __forceinline__ void cp16(void* dst, const void* src) {
    unsigned d = (unsigned)__cvta_generic_to_shared(dst);
    asm volatile("cp.async.cg.shared.global [%0], [%1], 16;\n" :: "r"(d), "l"(src));
}
__device__ __forceinline__ void cp_commit() { asm volatile("cp.async.commit_group;\n" ::); }
__device__ __forceinline__ void cp_wait0()  { asm volatile("cp.async.wait_group 0;\n" ::); }
__device__ __forceinline__ void cp_wait1()  { asm volatile("cp.async.wait_group 1;\n" ::); }

__device__ __forceinline__ uint2 pack4(float a, float b, float c, float d) {
    __nv_bfloat162 lo = __floats2bfloat162_rn(a, b);
    __nv_bfloat162 hi = __floats2bfloat162_rn(c, d);
    uint2 r; r.x = *(unsigned*)&lo; r.y = *(unsigned*)&hi; return r;
}
__device__ __forceinline__ unsigned packu(float a, float b) {
    __nv_bfloat162 t = __floats2bfloat162_rn(a, b);
    return *(unsigned*)&t;
}
__device__ __forceinline__ unsigned ex2_bf16x2(unsigned y) {
    unsigned r;
    asm("ex2.approx.ftz.bf16x2 %0, %1;" : "=r"(r) : "r"(y));
    return r;
}
__device__ __forceinline__ void mma16816(float* c, const unsigned* a, unsigned b0, unsigned b1) {
    asm volatile("mma.sync.aligned.m16n8k16.row.col.f32.bf16.bf16.f32 "
                 "{%0,%1,%2,%3}, {%4,%5,%6,%7}, {%8,%9}, {%0,%1,%2,%3};\n"
                 : "+f"(c[0]), "+f"(c[1]), "+f"(c[2]), "+f"(c[3])
                 : "r"(a[0]), "r"(a[1]), "r"(a[2]), "r"(a[3]), "r"(b0), "r"(b1));
}
__device__ __forceinline__ void ldsm4(unsigned* r, unsigned addr) {
    asm volatile("ldmatrix.sync.aligned.m8n8.x4.shared.b16 {%0,%1,%2,%3}, [%4];\n"
                 : "=r"(r[0]), "=r"(r[1]), "=r"(r[2]), "=r"(r[3]) : "r"(addr));
}
__device__ __forceinline__ void ldsm4t(unsigned* r, unsigned addr) {
    asm volatile("ldmatrix.sync.aligned.m8n8.x4.trans.shared.b16 {%0,%1,%2,%3}, [%4];\n"
                 : "=r"(r[0]), "=r"(r[1]), "=r"(r[2]), "=r"(r[3]) : "r"(addr));
}

// ========= fused pre-kernel: GroupNorm (blocks 0-255) + weight conv (256-767) =========
__global__ void pre_kernel(const float* __restrict__ x,
                           const float* __restrict__ gamma,
                           const float* __restrict__ beta,
                           const float* __restrict__ wq,
                           const float* __restrict__ wp) {
    if (blockIdx.x >= 256) {
        int i = (blockIdx.x - 256) * 512 + threadIdx.x;
        const float* s; bf16* d; int j;
        if (i < 196608) { s = wq; d = g_wq; j = i; }
        else            { s = wp; d = g_wp; j = i - 196608; }
        float4 v = ((const float4*)s)[j];
        ((uint2*)d)[j] = pack4(v.x, v.y, v.z, v.w);
        return;
    }
    int bg = blockIdx.x;
    int b = bg >> 5, g = bg & 31;
    size_t base = ((size_t)(b * C_ + g * 16)) * HW;
    const float4* xin = (const float4*)(x + base);

    float4 vr[8];
    float s = 0.f, s2 = 0.f;
    #pragma unroll
    for (int u = 0; u < 8; u++) {
        float4 v = xin[threadIdx.x + u * 512];
        vr[u] = v;
        s  += v.x + v.y + v.z + v.w;
        s2 += v.x * v.x + v.y * v.y + v.z * v.z + v.w * v.w;
    }
    __shared__ float red[2][16];
    #pragma unroll
    for (int o = 16; o; o >>= 1) {
        s  += __shfl_xor_sync(~0u, s, o);
        s2 += __shfl_xor_sync(~0u, s2, o);
    }
    int w = threadIdx.x >> 5, l = threadIdx.x & 31;
    if (l == 0) { red[0][w] = s; red[1][w] = s2; }
    __syncthreads();
    if (threadIdx.x == 0) {
        float ts = 0.f, ts2 = 0.f;
        #pragma unroll
        for (int i = 0; i < 16; i++) { ts += red[0][i]; ts2 += red[1][i]; }
        float mu  = ts / 16384.f;
        float var = ts2 / 16384.f - mu * mu;
        red[0][0] = mu;
        red[1][0] = rsqrtf(var + 1e-5f);
    }
    __syncthreads();
    float mu = red[0][0], rstd = red[1][0];
    uint2* outp = (uint2*)(g_h + base);
    #pragma unroll
    for (int u = 0; u < 8; u++) {
        int q = threadIdx.x + u * 512;
        float4 v = vr[u];
        int c = g * 16 + (q >> 8);
        float ga = gamma[c] * rstd;
        float be = beta[c] - mu * ga;
        outp[q] = pack4(v.x * ga + be, v.y * ga + be, v.z * ga + be, v.w * ga + be);
    }
}

// ====== Raw-mma GEMM: 128x128 block, BK=64, 3-stage ring (8 barrier phases) ======
// 8 warps as 4(m)x2(n), warp tile 32x64; 2 CTAs/SM.
template <bool RES>
__global__ __launch_bounds__(256, 2)
void gemm_mma(const bf16* __restrict__ in, const bf16* __restrict__ w,
              const float* __restrict__ bias, const float* __restrict__ res,
              void* __restrict__ outv, int OC) {
    extern __shared__ char smc[];
    // stage layout: A [128][72] bf16 (18432 B) + B [64][136] bf16 (17408 B)
    const int STG = 35840;

    int b = blockIdx.z;
    int o0 = blockIdx.y * 128, p0 = blockIdx.x * 128;
    int tid = threadIdx.x, wid = tid >> 5, lane = tid & 31;
    int wm = wid >> 1, wn = wid & 1;
    int l16 = lane & 15, lhi = lane >> 4;

    const bf16* wbase = w + (size_t)o0 * C_;
    const bf16* ibase = in + ((size_t)b * C_) * HW + p0;

    float acc[2][8][4] = {};

    auto issue = [&](int it) {
        if (it < 8) {
            int bu = it % 3, c0 = it * 64;
            bf16* dA = (bf16*)(smc + bu * STG);
            bf16* dB = (bf16*)(smc + bu * STG + 18432);
            #pragma unroll
            for (int u = 0; u < 4; u++) {
                int idx = tid + u * 256;
                int o = idx >> 3, ch = (idx & 7) * 8;          // A: 128 rows x 8 chunks
                cp16(dA + o * 72 + ch, wbase + (size_t)o * C_ + c0 + ch);
                int k = idx >> 4, jq = (idx & 15) * 8;         // B: 64 rows x 16 chunks
                cp16(dB + k * 136 + jq, ibase + (size_t)(c0 + k) * HW + jq);
            }
        }
        cp_commit();
    };

    issue(0); issue(1);
    unsigned sbase = (unsigned)__cvta_generic_to_shared(smc);

    for (int it = 0; it < 8; it++) {
        if (it < 7) cp_wait1(); else cp_wait0();
        __syncthreads();
        issue(it + 2);
        unsigned A  = sbase + (it % 3) * STG;
        unsigned Bb = A + 18432;
        #pragma unroll
        for (int kk = 0; kk < 4; kk++) {
            unsigned aq[2][4];
            #pragma unroll
            for (int mi = 0; mi < 2; mi++)
                ldsm4(aq[mi], A + ((wm * 32 + mi * 16 + l16) * 72 + kk * 16) * 2 + lhi * 16);
            #pragma unroll
            for (int dn2 = 0; dn2 < 4; dn2++) {
                unsigned bq[4];
                ldsm4t(bq, Bb + ((kk * 16 + l16) * 136 + wn * 64 + dn2 * 16) * 2 + lhi * 16);
                #pragma unroll
                for (int mi = 0; mi < 2; mi++) {
                    mma16816(acc[mi][2 * dn2],     aq[mi], bq[0], bq[1]);
                    mma16816(acc[mi][2 * dn2 + 1], aq[mi], bq[2], bq[3]);
                }
            }
        }
    }

    #pragma unroll
    for (int mi = 0; mi < 2; mi++) {
        int ro = o0 + wm * 32 + mi * 16 + (lane >> 2);
        float b0 = bias[ro], b1 = bias[ro + 8];
        size_t a0 = ((size_t)b * OC + ro) * HW + p0 + wn * 64 + (lane & 3) * 2;
        size_t a1 = a0 + 8 * HW;
        #pragma unroll
        for (int dn = 0; dn < 8; dn++) {
            size_t off = dn * 8;
            if (RES) {
                float* of = (float*)outv;
                float2 r0 = *(const float2*)&res[a0 + off];
                float2 r1 = *(const float2*)&res[a1 + off];
                float2 v0 = {acc[mi][dn][0] + b0 + r0.x, acc[mi][dn][1] + b0 + r0.y};
                float2 v1 = {acc[mi][dn][2] + b1 + r1.x, acc[mi][dn][3] + b1 + r1.y};
                *(float2*)&of[a0 + off] = v0;
                *(float2*)&of[a1 + off] = v1;
            } else {
                bf16* ob = (bf16*)outv;
                *(unsigned*)&ob[a0 + off] = packu(acc[mi][dn][0] + b0, acc[mi][dn][1] + b0);
                *(unsigned*)&ob[a1 + off] = packu(acc[mi][dn][2] + b1, acc[mi][dn][3] + b1);
            }
        }
    }
}

// ======================= Raw-mma FA2-style attention (round-10 winner) ==========
__global__ __launch_bounds__(128, 2) void attn_mma() {
    extern __shared__ char smc[];
    bf16* sQ = (bf16*)smc;                    // [128][72]
    bf16* sK = (bf16*)(smc + 18432);          // [3][64][72]
    bf16* sV = (bf16*)(smc + 18432 + 27648);  // [3][64][72]

    int bh = blockIdx.y;
    int b = bh >> 3, nh = bh & 7;
    int i0 = blockIdx.x * 128;
    int tid = threadIdx.x, wid = tid >> 5, lane = tid & 31;

    const bf16* qptr = g_qkv + ((size_t)(b * OC_QKV + nh * DH)) * HW + i0;
    const bf16* kptr = g_qkv + ((size_t)(b * OC_QKV + C_ + nh * DH)) * HW;
    const bf16* vptr = g_qkv + ((size_t)(b * OC_QKV + 2 * C_ + nh * DH)) * HW;

    auto issueKV = [&](int it) {
        int bu = it % 3, j0 = it * 64;
        bf16* dK = sK + bu * 4608;
        bf16* dV = sV + bu * 4608;
        #pragma unroll
        for (int u = 0; u < 4; u++) {
            int idx = tid + u * 128;
            int d = idx >> 3, jq = (idx & 7) * 8;
            cp16(dK + d * 72 + jq, kptr + (size_t)d * HW + j0 + jq);
            cp16(dV + d * 72 + jq, vptr + (size_t)d * HW + j0 + jq);
        }
        cp_commit();
    };

    issueKV(0); issueKV(1);

    const float QSCALE = 0.125f * 1.4426950408889634f;
    for (int e = tid; e < 1024; e += 128) {
        int d = e >> 4, i8 = (e & 15) * 8;
        uint4 v = *(const uint4*)&qptr[(size_t)d * HW + i8];
        bf16 tmp[8]; *(uint4*)tmp = v;
        #pragma unroll
        for (int z = 0; z < 8; z++)
            sQ[(i8 + z) * 72 + d] = __float2bfloat16(__bfloat162float(tmp[z]) * QSCALE);
    }
    __syncthreads();

    unsigned aq[2][4][4];
    {
        unsigned qb = (unsigned)__cvta_generic_to_shared(sQ);
        #pragma unroll
        for (int mi = 0; mi < 2; mi++) {
            unsigned rowaddr = qb +
                ((wid * 32 + mi * 16 + (lane & 15)) * 72 + (lane >> 4) * 8) * 2;
            #pragma unroll
            for (int kk = 0; kk < 4; kk++) ldsm4(aq[mi][kk], rowaddr + kk * 32);
        }
    }

    float co[2][8][4] = {};
    float crow[2][4] = {};
    unsigned kb0 = (unsigned)__cvta_generic_to_shared(sK);
    unsigned vb0 = (unsigned)__cvta_generic_to_shared(sV);
    int l16 = lane & 15, lr8 = lane & 7, half8 = ((lane >> 3) & 1) * 8;
    int joff16 = (lane >> 4) * 16;
    int doff   = (lane >> 4) * (8 * 72 * 2);
    unsigned ones_b = (lane < 4) ? 0x3F803F80u : 0u;

    for (int it = 0; it < 16; it++) {
        if (it < 15) cp_wait1(); else cp_wait0();
        __syncthreads();
        if (it + 2 < 16) issueKV(it + 2);
        unsigned kb = kb0 + (it % 3) * 9216;
        unsigned vb = vb0 + (it % 3) * 9216;

        float cs[2][8][4] = {};
        #pragma unroll
        for (int kk = 0; kk < 4; kk++) {
            unsigned ka = kb + ((kk * 16 + l16) * 72) * 2 + joff16;
            #pragma unroll
            for (int jn = 0; jn < 8; jn += 2) {
                unsigned r[4];
                ldsm4t(r, ka + jn * 16);
                #pragma unroll
                for (int mi = 0; mi < 2; mi++) {
                    mma16816(cs[mi][jn],     aq[mi][kk], r[0], r[1]);
                    mma16816(cs[mi][jn + 1], aq[mi][kk], r[2], r[3]);
                }
            }
        }

        unsigned ap[2][4][4];
        #pragma unroll
        for (int mi = 0; mi < 2; mi++) {
            #pragma unroll
            for (int t = 0; t < 4; t++) {
                ap[mi][t][0] = ex2_bf16x2(packu(cs[mi][2 * t][0],     cs[mi][2 * t][1]));
                ap[mi][t][1] = ex2_bf16x2(packu(cs[mi][2 * t][2],     cs[mi][2 * t][3]));
                ap[mi][t][2] = ex2_bf16x2(packu(cs[mi][2 * t + 1][0], cs[mi][2 * t + 1][1]));
                ap[mi][t][3] = ex2_bf16x2(packu(cs[mi][2 * t + 1][2], cs[mi][2 * t + 1][3]));
                mma16816(crow[mi], ap[mi][t], ones_b, ones_b);
            }
        }

        #pragma unroll
        for (int t = 0; t < 4; t++) {
            unsigned va = vb + (lr8 * 72 + t * 16 + half8) * 2 + doff;
            #pragma unroll
            for (int dn = 0; dn < 8; dn += 2) {
                unsigned r[4];
                ldsm4(r, va + dn * 8 * 72 * 2);
                #pragma unroll
                for (int mi = 0; mi < 2; mi++) {
                    mma16816(co[mi][dn],     ap[mi][t], r[0], r[1]);
                    mma16816(co[mi][dn + 1], ap[mi][t], r[2], r[3]);
                }
            }
        }
    }

    #pragma unroll
    for (int mi = 0; mi < 2; mi++) {
        float inv0 = 1.f / __shfl_sync(~0u, crow[mi][0], lane & 28);
        float inv1 = 1.f / __shfl_sync(~0u, crow[mi][2], lane & 28);
        int ir0 = i0 + wid * 32 + mi * 16 + (lane >> 2);
        int ir1 = ir0 + 8;
        size_t a0 = ((size_t)(b * C_ + nh * 64 + (ir0 >> 4))) * HW + (ir0 & 15) * 64;
        size_t a1 = ((size_t)(b * C_ + nh * 64 + (ir1 >> 4))) * HW + (ir1 & 15) * 64;
        #pragma unroll
        for (int dn = 0; dn < 8; dn++) {
            int d = dn * 8 + (lane & 3) * 2;
            *(unsigned*)&g_att[a0 + d] = packu(co[mi][dn][0] * inv0, co[mi][dn][1] * inv0);
            *(unsigned*)&g_att[a1 + d] = packu(co[mi][dn][2] * inv1, co[mi][dn][3] * inv1);
        }
    }
}

// ============================ launch ============================
extern "C" void kernel_launch(void* const* d_in, const int* in_sizes, int n_in,
                              void* d_out, int out_size) {
    const float* x      = (const float*)d_in[0];
    const float* gamma  = (const float*)d_in[1];
    const float* beta   = (const float*)d_in[2];
    const float* qkv_w  = (const float*)d_in[3];
    const float* qkv_b  = (const float*)d_in[4];
    const float* proj_w = (const float*)d_in[5];
    const float* proj_b = (const float*)d_in[6];
    float* out = (float*)d_out;

    void *p_h, *p_qkv, *p_att, *p_wq, *p_wp;
    cudaGetSymbolAddress(&p_h, g_h);
    cudaGetSymbolAddress(&p_qkv, g_qkv);
    cudaGetSymbolAddress(&p_att, g_att);
    cudaGetSymbolAddress(&p_wq, g_wq);
    cudaGetSymbolAddress(&p_wp, g_wp);

    const int GEMM_SMEM = 3 * 35840;           // 107520
    const int ATTN_SMEM = 18432 + 2 * 27648;   // 73728
    cudaFuncSetAttribute(gemm_mma<false>,
                         cudaFuncAttributeMaxDynamicSharedMemorySize, GEMM_SMEM);
    cudaFuncSetAttribute(gemm_mma<true>,
                         cudaFuncAttributeMaxDynamicSharedMemorySize, GEMM_SMEM);
    cudaFuncSetAttribute(attn_mma,
                         cudaFuncAttributeMaxDynamicSharedMemorySize, ATTN_SMEM);

    // fused GroupNorm + weight conversion (one launch)
    pre_kernel<<<768, 512>>>(x, gamma, beta, qkv_w, proj_w);

    gemm_mma<false><<<dim3(8, 12, B_), 256, GEMM_SMEM>>>(
        (const bf16*)p_h, (const bf16*)p_wq, qkv_b, nullptr, p_qkv, OC_QKV);

    attn_mma<<<dim3(8, 64), 128, ATTN_SMEM>>>();

    gemm_mma<true><<<dim3(8, 4, B_), 256, GEMM_SMEM>>>(
        (const bf16*)p_att, (const bf16*)p_wp, proj_b, x, out, C_);
}

// round 17
// speedup vs baseline: 1.0927x; 1.0927x over previous
#include <cuda_runtime.h>
#include <cuda_bf16.h>

#define B_ 8
#define C_ 512
#define HW 1024
#define NH 8
#define DH 64
#define OC_QKV 1536

typedef __nv_bfloat16 bf16;

// -------- scratch (static device globals; no allocation) --------
__device__ bf16 g_h[B_ * C_ * HW];
__device__ bf16 g_qkv[B_ * OC_QKV * HW];
__device__ bf16 g_att[B_ * C_ * HW];
__device__ bf16 g_wq[OC_QKV * C_];
__device__ bf16 g_wp[C_ * C_];

// -------- helpers --------
__device__ __forceinline__ void cp16(void* dst, const void* src) {
    unsigned d = (unsigned)__cvta_generic_to_shared(dst);
    asm volatile("cp.async.cg.shared.global [%0], [%1], 16;\n" :: "r"(d), "l"(src));
}
__device__ __forceinline__ void cp_commit() { asm volatile("cp.async.commit_group;\n" ::); }
__device__ __forceinline__ void cp_wait0()  { asm volatile("cp.async.wait_group 0;\n" ::); }
__device__ __forceinline__ void cp_wait1()  { asm volatile("cp.async.wait_group 1;\n" ::); }
__device__ __forceinline__ void cp_wait3()  { asm volatile("cp.async.wait_group 3;\n" ::); }

__device__ __forceinline__ uint2 pack4(float a, float b, float c, float d) {
    __nv_bfloat162 lo = __floats2bfloat162_rn(a, b);
    __nv_bfloat162 hi = __floats2bfloat162_rn(c, d);
    uint2 r; r.x = *(unsigned*)&lo; r.y = *(unsigned*)&hi; return r;
}
__device__ __forceinline__ unsigned packu(float a, float b) {
    __nv_bfloat162 t = __floats2bfloat162_rn(a, b);
    return *(unsigned*)&t;
}
__device__ __forceinline__ unsigned ex2_bf16x2(unsigned y) {
    unsigned r;
    asm("ex2.approx.ftz.bf16x2 %0, %1;" : "=r"(r) : "r"(y));
    return r;
}
__device__ __forceinline__ void mma16816(float* c, const unsigned* a, unsigned b0, unsigned b1) {
    asm volatile("mma.sync.aligned.m16n8k16.row.col.f32.bf16.bf16.f32 "
                 "{%0,%1,%2,%3}, {%4,%5,%6,%7}, {%8,%9}, {%0,%1,%2,%3};\n"
                 : "+f"(c[0]), "+f"(c[1]), "+f"(c[2]), "+f"(c[3])
                 : "r"(a[0]), "r"(a[1]), "r"(a[2]), "r"(a[3]), "r"(b0), "r"(b1));
}
__device__ __forceinline__ void ldsm4(unsigned* r, unsigned addr) {
    asm volatile("ldmatrix.sync.aligned.m8n8.x4.shared.b16 {%0,%1,%2,%3}, [%4];\n"
                 : "=r"(r[0]), "=r"(r[1]), "=r"(r[2]), "=r"(r[3]) : "r"(addr));
}
__device__ __forceinline__ void ldsm4t(unsigned* r, unsigned addr) {
    asm volatile("ldmatrix.sync.aligned.m8n8.x4.trans.shared.b16 {%0,%1,%2,%3}, [%4];\n"
                 : "=r"(r[0]), "=r"(r[1]), "=r"(r[2]), "=r"(r[3]) : "r"(addr));
}

// ========= fused pre-kernel: GroupNorm (blocks 0-255) + weight conv (256-767) =========
__global__ void pre_kernel(const float* __restrict__ x,
                           const float* __restrict__ gamma,
                           const float* __restrict__ beta,
                           const float* __restrict__ wq,
                           const float* __restrict__ wp) {
    if (blockIdx.x >= 256) {
        int i = (blockIdx.x - 256) * 512 + threadIdx.x;
        const float* s; bf16* d; int j;
        if (i < 196608) { s = wq; d = g_wq; j = i; }
        else            { s = wp; d = g_wp; j = i - 196608; }
        float4 v = ((const float4*)s)[j];
        ((uint2*)d)[j] = pack4(v.x, v.y, v.z, v.w);
        return;
    }
    int bg = blockIdx.x;
    int b = bg >> 5, g = bg & 31;
    size_t base = ((size_t)(b * C_ + g * 16)) * HW;
    const float4* xin = (const float4*)(x + base);

    float4 vr[8];
    float s = 0.f, s2 = 0.f;
    #pragma unroll
    for (int u = 0; u < 8; u++) {
        float4 v = xin[threadIdx.x + u * 512];
        vr[u] = v;
        s  += v.x + v.y + v.z + v.w;
        s2 += v.x * v.x + v.y * v.y + v.z * v.z + v.w * v.w;
    }
    __shared__ float red[2][16];
    #pragma unroll
    for (int o = 16; o; o >>= 1) {
        s  += __shfl_xor_sync(~0u, s, o);
        s2 += __shfl_xor_sync(~0u, s2, o);
    }
    int w = threadIdx.x >> 5, l = threadIdx.x & 31;
    if (l == 0) { red[0][w] = s; red[1][w] = s2; }
    __syncthreads();
    if (threadIdx.x == 0) {
        float ts = 0.f, ts2 = 0.f;
        #pragma unroll
        for (int i = 0; i < 16; i++) { ts += red[0][i]; ts2 += red[1][i]; }
        float mu  = ts / 16384.f;
        float var = ts2 / 16384.f - mu * mu;
        red[0][0] = mu;
        red[1][0] = rsqrtf(var + 1e-5f);
    }
    __syncthreads();
    float mu = red[0][0], rstd = red[1][0];
    uint2* outp = (uint2*)(g_h + base);
    #pragma unroll
    for (int u = 0; u < 8; u++) {
        int q = threadIdx.x + u * 512;
        float4 v = vr[u];
        int c = g * 16 + (q >> 8);
        float ga = gamma[c] * rstd;
        float be = beta[c] - mu * ga;
        outp[q] = pack4(v.x * ga + be, v.y * ga + be, v.z * ga + be, v.w * ga + be);
    }
}

// =============== Raw-mma GEMM (round-15 proven): 128x128, BK=32, 5-stage ring ======
template <bool RES>
__global__ __launch_bounds__(256, 2)
void gemm_mma(const bf16* __restrict__ in, const bf16* __restrict__ w,
              const float* __restrict__ bias, const float* __restrict__ res,
              void* __restrict__ outv, int OC, int bfirst) {
    extern __shared__ char smc[];
    bf16* sA = (bf16*)smc;              // [5][128][40]
    bf16* sB = (bf16*)(smc + 51200);    // [5][32][136]

    int b = bfirst + blockIdx.z;
    int o0 = blockIdx.y * 128, p0 = blockIdx.x * 128;
    int tid = threadIdx.x, wid = tid >> 5, lane = tid & 31;
    int wm = wid >> 1, wn = wid & 1;
    int l16 = lane & 15, lhi = lane >> 4;

    const bf16* wbase = w + (size_t)o0 * C_;
    const bf16* ibase = in + ((size_t)b * C_) * HW + p0;

    float acc[2][8][4] = {};

    auto issue = [&](int it) {
        if (it < 16) {
            int bu = it % 5, c0 = it * 32;
            bf16* dA = sA + bu * 5120;
            bf16* dB = sB + bu * 4352;
            #pragma unroll
            for (int u = 0; u < 2; u++) {
                int idx = tid + u * 256;
                int o = idx >> 2, kq = (idx & 3) * 8;
                cp16(dA + o * 40 + kq, wbase + (size_t)o * C_ + c0 + kq);
                int k = idx >> 4, jq = (idx & 15) * 8;
                cp16(dB + k * 136 + jq, ibase + (size_t)(c0 + k) * HW + jq);
            }
        }
        cp_commit();
    };

    issue(0); issue(1); issue(2); issue(3);
    unsigned abase = (unsigned)__cvta_generic_to_shared(sA);
    unsigned bbase = (unsigned)__cvta_generic_to_shared(sB);

    for (int it = 0; it < 16; it++) {
        cp_wait3();
        __syncthreads();
        issue(it + 4);
        unsigned A  = abase + (it % 5) * 10240;
        unsigned Bb = bbase + (it % 5) * 8704;
        #pragma unroll
        for (int kk = 0; kk < 2; kk++) {
            unsigned aq[2][4];
            #pragma unroll
            for (int mi = 0; mi < 2; mi++)
                ldsm4(aq[mi], A + ((wm * 32 + mi * 16 + l16) * 40 + kk * 16) * 2 + lhi * 16);
            #pragma unroll
            for (int dn2 = 0; dn2 < 4; dn2++) {
                unsigned bq[4];
                ldsm4t(bq, Bb + ((kk * 16 + l16) * 136 + wn * 64 + dn2 * 16) * 2 + lhi * 16);
                #pragma unroll
                for (int mi = 0; mi < 2; mi++) {
                    mma16816(acc[mi][2 * dn2],     aq[mi], bq[0], bq[1]);
                    mma16816(acc[mi][2 * dn2 + 1], aq[mi], bq[2], bq[3]);
                }
            }
        }
    }

    #pragma unroll
    for (int mi = 0; mi < 2; mi++) {
        int ro = o0 + wm * 32 + mi * 16 + (lane >> 2);
        float b0 = bias[ro], b1 = bias[ro + 8];
        size_t a0 = ((size_t)b * OC + ro) * HW + p0 + wn * 64 + (lane & 3) * 2;
        size_t a1 = a0 + 8 * HW;
        #pragma unroll
        for (int dn = 0; dn < 8; dn++) {
            size_t off = dn * 8;
            if (RES) {
                float* of = (float*)outv;
                float2 r0 = *(const float2*)&res[a0 + off];
                float2 r1 = *(const float2*)&res[a1 + off];
                float2 v0 = {acc[mi][dn][0] + b0 + r0.x, acc[mi][dn][1] + b0 + r0.y};
                float2 v1 = {acc[mi][dn][2] + b1 + r1.x, acc[mi][dn][3] + b1 + r1.y};
                *(float2*)&of[a0 + off] = v0;
                *(float2*)&of[a1 + off] = v1;
            } else {
                bf16* ob = (bf16*)outv;
                *(unsigned*)&ob[a0 + off] = packu(acc[mi][dn][0] + b0, acc[mi][dn][1] + b0);
                *(unsigned*)&ob[a1 + off] = packu(acc[mi][dn][2] + b1, acc[mi][dn][3] + b1);
            }
        }
    }
}

// ======================= Raw-mma FA2-style attention (round-10 winner) ==========
__global__ __launch_bounds__(128, 2) void attn_mma(int bfirst) {
    extern __shared__ char smc[];
    bf16* sQ = (bf16*)smc;                    // [128][72]
    bf16* sK = (bf16*)(smc + 18432);          // [3][64][72]
    bf16* sV = (bf16*)(smc + 18432 + 27648);  // [3][64][72]

    int bh = blockIdx.y;
    int b = bfirst + (bh >> 3), nh = bh & 7;
    int i0 = blockIdx.x * 128;
    int tid = threadIdx.x, wid = tid >> 5, lane = tid & 31;

    const bf16* qptr = g_qkv + ((size_t)(b * OC_QKV + nh * DH)) * HW + i0;
    const bf16* kptr = g_qkv + ((size_t)(b * OC_QKV + C_ + nh * DH)) * HW;
    const bf16* vptr = g_qkv + ((size_t)(b * OC_QKV + 2 * C_ + nh * DH)) * HW;

    auto issueKV = [&](int it) {
        int bu = it % 3, j0 = it * 64;
        bf16* dK = sK + bu * 4608;
        bf16* dV = sV + bu * 4608;
        #pragma unroll
        for (int u = 0; u < 4; u++) {
            int idx = tid + u * 128;
            int d = idx >> 3, jq = (idx & 7) * 8;
            cp16(dK + d * 72 + jq, kptr + (size_t)d * HW + j0 + jq);
            cp16(dV + d * 72 + jq, vptr + (size_t)d * HW + j0 + jq);
        }
        cp_commit();
    };

    issueKV(0); issueKV(1);

    const float QSCALE = 0.125f * 1.4426950408889634f;
    for (int e = tid; e < 1024; e += 128) {
        int d = e >> 4, i8 = (e & 15) * 8;
        uint4 v = *(const uint4*)&qptr[(size_t)d * HW + i8];
        bf16 tmp[8]; *(uint4*)tmp = v;
        #pragma unroll
        for (int z = 0; z < 8; z++)
            sQ[(i8 + z) * 72 + d] = __float2bfloat16(__bfloat162float(tmp[z]) * QSCALE);
    }
    __syncthreads();

    unsigned aq[2][4][4];
    {
        unsigned qb = (unsigned)__cvta_generic_to_shared(sQ);
        #pragma unroll
        for (int mi = 0; mi < 2; mi++) {
            unsigned rowaddr = qb +
                ((wid * 32 + mi * 16 + (lane & 15)) * 72 + (lane >> 4) * 8) * 2;
            #pragma unroll
            for (int kk = 0; kk < 4; kk++) ldsm4(aq[mi][kk], rowaddr + kk * 32);
        }
    }

    float co[2][8][4] = {};
    float crow[2][4] = {};
    unsigned kb0 = (unsigned)__cvta_generic_to_shared(sK);
    unsigned vb0 = (unsigned)__cvta_generic_to_shared(sV);
    int l16 = lane & 15, lr8 = lane & 7, half8 = ((lane >> 3) & 1) * 8;
    int joff16 = (lane >> 4) * 16;
    int doff   = (lane >> 4) * (8 * 72 * 2);
    unsigned ones_b = (lane < 4) ? 0x3F803F80u : 0u;

    for (int it = 0; it < 16; it++) {
        if (it < 15) cp_wait1(); else cp_wait0();
        __syncthreads();
        if (it + 2 < 16) issueKV(it + 2);
        unsigned kb = kb0 + (it % 3) * 9216;
        unsigned vb = vb0 + (it % 3) * 9216;

        float cs[2][8][4] = {};
        #pragma unroll
        for (int kk = 0; kk < 4; kk++) {
            unsigned ka = kb + ((kk * 16 + l16) * 72) * 2 + joff16;
            #pragma unroll
            for (int jn = 0; jn < 8; jn += 2) {
                unsigned r[4];
                ldsm4t(r, ka + jn * 16);
                #pragma unroll
                for (int mi = 0; mi < 2; mi++) {
                    mma16816(cs[mi][jn],     aq[mi][kk], r[0], r[1]);
                    mma16816(cs[mi][jn + 1], aq[mi][kk], r[2], r[3]);
                }
            }
        }

        unsigned ap[2][4][4];
        #pragma unroll
        for (int mi = 0; mi < 2; mi++) {
            #pragma unroll
            for (int t = 0; t < 4; t++) {
                ap[mi][t][0] = ex2_bf16x2(packu(cs[mi][2 * t][0],     cs[mi][2 * t][1]));
                ap[mi][t][1] = ex2_bf16x2(packu(cs[mi][2 * t][2],     cs[mi][2 * t][3]));
                ap[mi][t][2] = ex2_bf16x2(packu(cs[mi][2 * t + 1][0], cs[mi][2 * t + 1][1]));
                ap[mi][t][3] = ex2_bf16x2(packu(cs[mi][2 * t + 1][2], cs[mi][2 * t + 1][3]));
                mma16816(crow[mi], ap[mi][t], ones_b, ones_b);
            }
        }

        #pragma unroll
        for (int t = 0; t < 4; t++) {
            unsigned va = vb + (lr8 * 72 + t * 16 + half8) * 2 + doff;
            #pragma unroll
            for (int dn = 0; dn < 8; dn += 2) {
                unsigned r[4];
                ldsm4(r, va + dn * 8 * 72 * 2);
                #pragma unroll
                for (int mi = 0; mi < 2; mi++) {
                    mma16816(co[mi][dn],     ap[mi][t], r[0], r[1]);
                    mma16816(co[mi][dn + 1], ap[mi][t], r[2], r[3]);
                }
            }
        }
    }

    #pragma unroll
    for (int mi = 0; mi < 2; mi++) {
        float inv0 = 1.f / __shfl_sync(~0u, crow[mi][0], lane & 28);
        float inv1 = 1.f / __shfl_sync(~0u, crow[mi][2], lane & 28);
        int ir0 = i0 + wid * 32 + mi * 16 + (lane >> 2);
        int ir1 = ir0 + 8;
        size_t a0 = ((size_t)(b * C_ + nh * 64 + (ir0 >> 4))) * HW + (ir0 & 15) * 64;
        size_t a1 = ((size_t)(b * C_ + nh * 64 + (ir1 >> 4))) * HW + (ir1 & 15) * 64;
        #pragma unroll
        for (int dn = 0; dn < 8; dn++) {
            int d = dn * 8 + (lane & 3) * 2;
            *(unsigned*)&g_att[a0 + d] = packu(co[mi][dn][0] * inv0, co[mi][dn][1] * inv0);
            *(unsigned*)&g_att[a1 + d] = packu(co[mi][dn][2] * inv1, co[mi][dn][3] * inv1);
        }
    }
}

// ============================ launch ============================
extern "C" void kernel_launch(void* const* d_in, const int* in_sizes, int n_in,
                              void* d_out, int out_size) {
    const float* x      = (const float*)d_in[0];
    const float* gamma  = (const float*)d_in[1];
    const float* beta   = (const float*)d_in[2];
    const float* qkv_w  = (const float*)d_in[3];
    const float* qkv_b  = (const float*)d_in[4];
    const float* proj_w = (const float*)d_in[5];
    const float* proj_b = (const float*)d_in[6];
    float* out = (float*)d_out;

    void *p_h, *p_qkv, *p_att, *p_wq, *p_wp;
    cudaGetSymbolAddress(&p_h, g_h);
    cudaGetSymbolAddress(&p_qkv, g_qkv);
    cudaGetSymbolAddress(&p_att, g_att);
    cudaGetSymbolAddress(&p_wq, g_wq);
    cudaGetSymbolAddress(&p_wp, g_wp);

    const int GEMM_SMEM = 94720;
    const int ATTN_SMEM = 18432 + 2 * 27648;   // 73728

    static cudaStream_t s1 = nullptr;
    static cudaEvent_t evPre = nullptr, evS1 = nullptr;
    if (!s1) {
        cudaStreamCreateWithFlags(&s1, cudaStreamNonBlocking);
        cudaEventCreateWithFlags(&evPre, cudaEventDisableTiming);
        cudaEventCreateWithFlags(&evS1, cudaEventDisableTiming);
        cudaFuncSetAttribute(gemm_mma<false>,
                             cudaFuncAttributeMaxDynamicSharedMemorySize, GEMM_SMEM);
        cudaFuncSetAttribute(gemm_mma<true>,
                             cudaFuncAttributeMaxDynamicSharedMemorySize, GEMM_SMEM);
        cudaFuncSetAttribute(attn_mma,
                             cudaFuncAttributeMaxDynamicSharedMemorySize, ATTN_SMEM);
    }

    // fused GroupNorm + weight conversion
    pre_kernel<<<768, 512>>>(x, gamma, beta, qkv_w, proj_w);

    // fork: batches 4-7 on s1
    cudaEventRecord(evPre, 0);
    cudaStreamWaitEvent(s1, evPre, 0);

    // ---- stream 0: batches 0-3 ----
    gemm_mma<false><<<dim3(8, 12, 4), 256, GEMM_SMEM>>>(
        (const bf16*)p_h, (const bf16*)p_wq, qkv_b, nullptr, p_qkv, OC_QKV, 0);
    attn_mma<<<dim3(8, 32), 128, ATTN_SMEM>>>(0);
    gemm_mma<true><<<dim3(8, 4, 4), 256, GEMM_SMEM>>>(
        (const bf16*)p_att, (const bf16*)p_wp, proj_b, x, out, C_, 0);

    // ---- stream s1: batches 4-7 ----
    gemm_mma<false><<<dim3(8, 12, 4), 256, GEMM_SMEM, s1>>>(
        (const bf16*)p_h, (const bf16*)p_wq, qkv_b, nullptr, p_qkv, OC_QKV, 4);
    attn_mma<<<dim3(8, 32), 128, ATTN_SMEM, s1>>>(4);
    gemm_mma<true><<<dim3(8, 4, 4), 256, GEMM_SMEM, s1>>>(
        (const bf16*)p_att, (const bf16*)p_wp, proj_b, x, out, C_, 4);

    // join
    cudaEventRecord(evS1, s1);
    cudaStreamWaitEvent(0, evS1, 0);
}